// round 1
// baseline (speedup 1.0000x reference)
#include <cuda_runtime.h>
#include <cuda_bf16.h>
#include <mma.h>
#include <math.h>

using namespace nvcuda;

// Problem constants
#define BB 32
#define NN 1024
#define DD 512
#define HH 8

// GEMM tiling
#define BM 128
#define BN 128
#define BK 32
#define LDSB 40           // BK + 8 pad (bf16 elems)
#define LDC  132          // BN + 4 pad (fp32 elems)
#define NTHREADS 256

// Scratch (device globals; allocation is forbidden)
__device__ float g_kh[(size_t)BB * HH * NN * DD];   // [B,H,N,D]
__device__ float g_qh[(size_t)BB * HH * NN * DD];   // [B,H,N,D] (pre-scaled by 1/sqrt(D))
__device__ float g_vh[(size_t)BB * HH * NN * DD];   // [B,H,N,D]
__device__ float g_S [(size_t)BB * HH * NN * NN];   // [B,H,N,N] scores -> P in place
__device__ float g_O [(size_t)BB * NN * DD * HH];   // [B,N,D,H]  (cat layout)

// ---------------------------------------------------------------------------
// bf16x3 compensated GEMM: C[m,n] = sum_k A[m,k] * Bsrc(n,k)  (+ epilogue)
//   TRANSB=true : Bsrc element (n,k) at Bp[n*ldb + k]   (K-major rows)
//   TRANSB=false: Bsrc element (n,k) at Bp[k*ldb + n]   ([K, Ncols] layout)
// MODE 0: per-head projection. z=head. A=[32768,K] input, B=W+z*K*K, bias+z*DD,
//         out = (acc+bias)*scale scattered to [B,H,N,D]
// MODE 1: scores. z=bh. A=qh+z*N*D, B=kh+z*N*D, out = S+z*N*N plain
// MODE 2: PV. z=bh. A=P+z*N*N, B=vh+z*N*D (TRANSB=false), out scatter [B,N,D,H]
// MODE 3: out proj. A=[32768,4096], B=Wo, out = acc+bo to d_out
// ---------------------------------------------------------------------------
template<int MODE, bool TRANSB>
__global__ __launch_bounds__(NTHREADS, 1)
void gemm_bf16x3(const float* __restrict__ Ag,
                 const float* __restrict__ Bg,
                 float* __restrict__ Cg,
                 const float* __restrict__ bias,
                 int K, int ldb, float scale)
{
    extern __shared__ char smem_raw[];
    __nv_bfloat16* As_hi = reinterpret_cast<__nv_bfloat16*>(smem_raw);
    __nv_bfloat16* As_lo = As_hi + BM * LDSB;
    __nv_bfloat16* Bs_hi = As_lo + BM * LDSB;
    __nv_bfloat16* Bs_lo = Bs_hi + BN * LDSB;
    float* Cs = reinterpret_cast<float*>(smem_raw);   // aliased for epilogue

    const int tid = threadIdx.x;
    const int z  = blockIdx.z;
    const int m0 = blockIdx.x * BM;
    const int n0 = blockIdx.y * BN;

    const float* A;
    const float* Bp;
    if (MODE == 0)      { A = Ag;                         Bp = Bg + (size_t)z * K * K; }
    else if (MODE == 1) { A = Ag + (size_t)z * NN * DD;   Bp = Bg + (size_t)z * NN * DD; }
    else if (MODE == 2) { A = Ag + (size_t)z * NN * NN;   Bp = Bg + (size_t)z * NN * DD; }
    else                { A = Ag;                         Bp = Bg; }

    wmma::fragment<wmma::accumulator, 16, 16, 16, float> acc[2][4];
    #pragma unroll
    for (int i = 0; i < 2; i++)
        #pragma unroll
        for (int j = 0; j < 4; j++)
            wmma::fill_fragment(acc[i][j], 0.0f);

    const int warp = tid >> 5;
    const int wm = warp & 3;    // m-warp 0..3  -> rows wm*32
    const int wn = warp >> 2;   // n-warp 0..1  -> cols wn*64

    const int nk = K / BK;
    for (int kt = 0; kt < nk; kt++) {
        const int k0 = kt * BK;

        // ---- load + split A tile (BM x BK), lda = K ----
        #pragma unroll
        for (int it = 0; it < (BM * BK / 4) / NTHREADS; it++) {
            int i = tid + it * NTHREADS;
            int row = i >> 3;
            int col = (i & 7) * 4;
            float4 vv = *reinterpret_cast<const float4*>(
                A + (size_t)(m0 + row) * K + k0 + col);
            float xs[4] = {vv.x, vv.y, vv.z, vv.w};
            #pragma unroll
            for (int j = 0; j < 4; j++) {
                __nv_bfloat16 hi = __float2bfloat16(xs[j]);
                __nv_bfloat16 lo = __float2bfloat16(xs[j] - __bfloat162float(hi));
                As_hi[row * LDSB + col + j] = hi;
                As_lo[row * LDSB + col + j] = lo;
            }
        }

        // ---- load + split B tile ----
        if (TRANSB) {
            #pragma unroll
            for (int it = 0; it < (BN * BK / 4) / NTHREADS; it++) {
                int i = tid + it * NTHREADS;
                int row = i >> 3;
                int col = (i & 7) * 4;
                float4 vv = *reinterpret_cast<const float4*>(
                    Bp + (size_t)(n0 + row) * ldb + k0 + col);
                float xs[4] = {vv.x, vv.y, vv.z, vv.w};
                #pragma unroll
                for (int j = 0; j < 4; j++) {
                    __nv_bfloat16 hi = __float2bfloat16(xs[j]);
                    __nv_bfloat16 lo = __float2bfloat16(xs[j] - __bfloat162float(hi));
                    Bs_hi[row * LDSB + col + j] = hi;
                    Bs_lo[row * LDSB + col + j] = lo;
                }
            }
        } else {
            // Bsrc [K, Ncols]: read BK rows x BN cols coalesced, transpose into smem
            #pragma unroll
            for (int it = 0; it < (BK * BN / 4) / NTHREADS; it++) {
                int i = tid + it * NTHREADS;
                int krow = i >> 5;          // 0..31
                int col  = (i & 31) * 4;    // 0..124
                float4 vv = *reinterpret_cast<const float4*>(
                    Bp + (size_t)(k0 + krow) * ldb + n0 + col);
                float xs[4] = {vv.x, vv.y, vv.z, vv.w};
                #pragma unroll
                for (int j = 0; j < 4; j++) {
                    __nv_bfloat16 hi = __float2bfloat16(xs[j]);
                    __nv_bfloat16 lo = __float2bfloat16(xs[j] - __bfloat162float(hi));
                    Bs_hi[(col + j) * LDSB + krow] = hi;
                    Bs_lo[(col + j) * LDSB + krow] = lo;
                }
            }
        }
        __syncthreads();

        // ---- mma: 3-pass bf16x3 ----
        #pragma unroll
        for (int kk = 0; kk < BK / 16; kk++) {
            const int ks = kk * 16;
            wmma::fragment<wmma::matrix_a, 16, 16, 16, __nv_bfloat16, wmma::row_major> a_hi[2], a_lo[2];
            #pragma unroll
            for (int mt = 0; mt < 2; mt++) {
                wmma::load_matrix_sync(a_hi[mt], As_hi + (wm * 32 + mt * 16) * LDSB + ks, LDSB);
                wmma::load_matrix_sync(a_lo[mt], As_lo + (wm * 32 + mt * 16) * LDSB + ks, LDSB);
            }
            wmma::fragment<wmma::matrix_b, 16, 16, 16, __nv_bfloat16, wmma::col_major> b_hi[4], b_lo[4];
            #pragma unroll
            for (int nt = 0; nt < 4; nt++) {
                wmma::load_matrix_sync(b_hi[nt], Bs_hi + (wn * 64 + nt * 16) * LDSB + ks, LDSB);
                wmma::load_matrix_sync(b_lo[nt], Bs_lo + (wn * 64 + nt * 16) * LDSB + ks, LDSB);
            }
            #pragma unroll
            for (int mt = 0; mt < 2; mt++)
                #pragma unroll
                for (int nt = 0; nt < 4; nt++) {
                    wmma::mma_sync(acc[mt][nt], a_hi[mt], b_hi[nt], acc[mt][nt]);
                    wmma::mma_sync(acc[mt][nt], a_hi[mt], b_lo[nt], acc[mt][nt]);
                    wmma::mma_sync(acc[mt][nt], a_lo[mt], b_hi[nt], acc[mt][nt]);
                }
        }
        __syncthreads();
    }

    // ---- epilogue: stage C in smem, then scalar writes with mode logic ----
    #pragma unroll
    for (int mt = 0; mt < 2; mt++)
        #pragma unroll
        for (int nt = 0; nt < 4; nt++)
            wmma::store_matrix_sync(Cs + (wm * 32 + mt * 16) * LDC + wn * 64 + nt * 16,
                                    acc[mt][nt], LDC, wmma::mem_row_major);
    __syncthreads();

    for (int i = tid; i < BM * BN; i += NTHREADS) {
        int r = i >> 7;
        int c = i & 127;
        float val = Cs[r * LDC + c];
        int row = m0 + r;
        int col = n0 + c;
        if (MODE == 0) {
            val = (val + bias[(size_t)z * DD + col]) * scale;
            int b = row >> 10;            // row = b*NN + n
            int n = row & (NN - 1);
            Cg[((size_t)(b * HH + z) * NN + n) * DD + col] = val;
        } else if (MODE == 1) {
            Cg[(size_t)z * NN * NN + (size_t)row * NN + col] = val;
        } else if (MODE == 2) {
            int b = z >> 3;               // z = b*HH + h
            int h = z & 7;
            Cg[((size_t)(b * NN + row) * DD + col) * HH + h] = val;
        } else {
            Cg[(size_t)row * DD + col] = val + bias[col];
        }
    }
}

// ---------------------------------------------------------------------------
// Row softmax over S rows of length NN (in place). One block (256 thr) per row.
// ---------------------------------------------------------------------------
__global__ __launch_bounds__(256)
void softmax_rows(float* __restrict__ S)
{
    __shared__ float red_m[8];
    __shared__ float red_s[8];
    const size_t row = blockIdx.x;
    float* p = S + row * NN;
    float4 v = reinterpret_cast<float4*>(p)[threadIdx.x];

    float mx = fmaxf(fmaxf(v.x, v.y), fmaxf(v.z, v.w));
    #pragma unroll
    for (int o = 16; o > 0; o >>= 1)
        mx = fmaxf(mx, __shfl_xor_sync(0xffffffffu, mx, o));
    if ((threadIdx.x & 31) == 0) red_m[threadIdx.x >> 5] = mx;
    __syncthreads();
    float m = red_m[0];
    #pragma unroll
    for (int i = 1; i < 8; i++) m = fmaxf(m, red_m[i]);

    float e0 = expf(v.x - m);
    float e1 = expf(v.y - m);
    float e2 = expf(v.z - m);
    float e3 = expf(v.w - m);
    float s = (e0 + e1) + (e2 + e3);
    #pragma unroll
    for (int o = 16; o > 0; o >>= 1)
        s += __shfl_xor_sync(0xffffffffu, s, o);
    if ((threadIdx.x & 31) == 0) red_s[threadIdx.x >> 5] = s;
    __syncthreads();
    float tot = 0.0f;
    #pragma unroll
    for (int i = 0; i < 8; i++) tot += red_s[i];
    float inv = 1.0f / tot;

    v.x = e0 * inv; v.y = e1 * inv; v.z = e2 * inv; v.w = e3 * inv;
    reinterpret_cast<float4*>(p)[threadIdx.x] = v;
}

// ---------------------------------------------------------------------------
extern "C" void kernel_launch(void* const* d_in, const int* in_sizes, int n_in,
                              void* d_out, int out_size)
{
    const float* k  = (const float*)d_in[0];
    const float* v  = (const float*)d_in[1];
    const float* q  = (const float*)d_in[2];
    const float* Wk = (const float*)d_in[3];
    const float* bk = (const float*)d_in[4];
    const float* Wv = (const float*)d_in[5];
    const float* bv = (const float*)d_in[6];
    const float* Wq = (const float*)d_in[7];
    const float* bq = (const float*)d_in[8];
    const float* Wo = (const float*)d_in[9];
    const float* bo = (const float*)d_in[10];
    float* out = (float*)d_out;

    float *kh, *qh, *vh, *S, *O;
    cudaGetSymbolAddress((void**)&kh, g_kh);
    cudaGetSymbolAddress((void**)&qh, g_qh);
    cudaGetSymbolAddress((void**)&vh, g_vh);
    cudaGetSymbolAddress((void**)&S,  g_S);
    cudaGetSymbolAddress((void**)&O,  g_O);

    const size_t SMEM = (size_t)BM * LDC * sizeof(float);   // 67584 > 48K default
    cudaFuncSetAttribute(gemm_bf16x3<0, true >, cudaFuncAttributeMaxDynamicSharedMemorySize, (int)SMEM);
    cudaFuncSetAttribute(gemm_bf16x3<1, true >, cudaFuncAttributeMaxDynamicSharedMemorySize, (int)SMEM);
    cudaFuncSetAttribute(gemm_bf16x3<2, false>, cudaFuncAttributeMaxDynamicSharedMemorySize, (int)SMEM);
    cudaFuncSetAttribute(gemm_bf16x3<3, true >, cudaFuncAttributeMaxDynamicSharedMemorySize, (int)SMEM);

    dim3 blk(NTHREADS);
    const float inv_scale = 1.0f / sqrtf((float)DD);

    // 1) per-head projections: [32768,512] x [512,512]^T per head
    gemm_bf16x3<0, true ><<<dim3(256, 4, 8), blk, SMEM>>>(k, Wk, kh, bk, 512, 512, 1.0f);
    gemm_bf16x3<0, true ><<<dim3(256, 4, 8), blk, SMEM>>>(v, Wv, vh, bv, 512, 512, 1.0f);
    gemm_bf16x3<0, true ><<<dim3(256, 4, 8), blk, SMEM>>>(q, Wq, qh, bq, 512, 512, inv_scale);

    // 2) scores S = qh * kh^T per (b,h)   [1024,512] x [512,1024]
    gemm_bf16x3<1, true ><<<dim3(8, 8, 256), blk, SMEM>>>(qh, kh, S, nullptr, 512, 512, 1.0f);

    // 3) softmax rows (in place -> P)
    softmax_rows<<<BB * HH * NN, 256>>>(S);

    // 4) O = P * vh per (b,h)   [1024,1024] x [1024,512], scatter to cat layout
    gemm_bf16x3<2, false><<<dim3(8, 4, 256), blk, SMEM>>>(S, vh, O, nullptr, 1024, 512, 1.0f);

    // 5) rep = cat * Wo^T + bo   [32768,4096] x [4096,512]
    gemm_bf16x3<3, true ><<<dim3(256, 4, 1), blk, SMEM>>>(O, Wo, out, bo, 4096, 4096, 1.0f);
}